// round 13
// baseline (speedup 1.0000x reference)
#include <cuda_runtime.h>
#include <cuda_fp16.h>
#include <cstdint>

#define IN_F 4096
#define OUT_F 4096
#define M_TOTAL 16384

#define TILE_M 128
#define TILE_N 256
#define TILE_K 64                       // k elems per chunk
#define NC (IN_F / TILE_K)              // 64
#define THREADS 256

// smem layout (bytes):
//  A32: 2 stages x 128 rows x 256B  = 65536   (fp32 A, XOR-swizzled 16B slots)
//  B  : 3 stages x 256 rows x 128B  = 98304   (fp16 W)
//  A16: 2 bufs   x 128 rows x 128B  = 32768   (converted fp16 A)
#define A32_OFF 0
#define A32_STAGE 32768
#define B_OFF 65536
#define B_STAGE 32768
#define A16_OFF 163840
#define A16_BUF 16384
#define SMEM_TOTAL 196608

// ---------------- device scratch ----------------
__device__ __half g_Wh[(size_t)OUT_F * IN_F];

// ---------------- helpers ----------------
static __device__ __forceinline__ uint32_t smem_u32_of(const void* p) {
    uint32_t r;
    asm("{ .reg .u64 t; cvta.to.shared.u64 t, %1; cvt.u32.u64 %0, t; }" : "=r"(r) : "l"(p));
    return r;
}
static __device__ __forceinline__ void cp16(uint32_t dst, const void* src) {
    asm volatile("cp.async.cg.shared.global [%0], [%1], 16;" :: "r"(dst), "l"(src));
}
static __device__ __forceinline__ void ldsm4(uint32_t* r, uint32_t a) {
    asm volatile("ldmatrix.sync.aligned.m8n8.x4.shared.b16 {%0,%1,%2,%3}, [%4];"
                 : "=r"(r[0]), "=r"(r[1]), "=r"(r[2]), "=r"(r[3]) : "r"(a));
}
static __device__ __forceinline__ void mma_f16(float* d, const uint32_t* a,
                                               uint32_t b0, uint32_t b1) {
    asm volatile(
        "mma.sync.aligned.m16n8k16.row.col.f32.f16.f16.f32 "
        "{%0,%1,%2,%3}, {%4,%5,%6,%7}, {%8,%9}, {%0,%1,%2,%3};"
        : "+f"(d[0]), "+f"(d[1]), "+f"(d[2]), "+f"(d[3])
        : "r"(a[0]), "r"(a[1]), "r"(a[2]), "r"(a[3]), "r"(b0), "r"(b1));
}

// ---------------- prep kernel 1: fp32 -> fp16 convert (W only) ----------------
__global__ void prep_convert(const float* __restrict__ W) {
    const size_t NW4 = (size_t)OUT_F * IN_F / 4;
    for (size_t j = (size_t)blockIdx.x * blockDim.x + threadIdx.x; j < NW4;
         j += (size_t)gridDim.x * blockDim.x) {
        float4 v = reinterpret_cast<const float4*>(W)[j];
        __half2 p0 = __floats2half2_rn(v.x, v.y);
        __half2 p1 = __floats2half2_rn(v.z, v.w);
        reinterpret_cast<uint2*>(g_Wh)[j] =
            make_uint2(*reinterpret_cast<uint32_t*>(&p0), *reinterpret_cast<uint32_t*>(&p1));
    }
}

// ---------------- prep kernel 2: sorted scatter, unique-leader rewrite ----------------
__global__ void scatter_fix(const float* __restrict__ sw, const int* __restrict__ idx,
                            const float* __restrict__ W, int nnz) {
    int i = blockIdx.x * blockDim.x + threadIdx.x;
    if (i >= nnz) return;
    int v = idx[i];
    if (i > 0 && idx[i - 1] == v) return;  // not segment leader
    float s = sw[i];
    for (int j = i + 1; j < nnz && idx[j] == v; ++j) s += sw[j];
    g_Wh[v] = __float2half_rn(W[v] + s);
}

// ---------------- GEMM: out[m,n] = sum_k A[m,k]*W[n,k] + bias[n] ----------------
// 128x256 CTA tile, 8 warps (2x4) of 64x64 warp tiles.
// A arrives as fp32 via cp.async, converted fp16 in-smem; B fp16 via cp.async.
__global__ void __launch_bounds__(THREADS, 1)
gemm_kernel(const float* __restrict__ Afp, const float* __restrict__ bias,
            float* __restrict__ out) {
    extern __shared__ __align__(128) char smem[];
    const uint32_t sbase = smem_u32_of(smem);

    const int tid  = threadIdx.x;
    const int lane = tid & 31;
    const int wid  = tid >> 5;        // 8 warps
    const int wm   = wid & 1;         // 2 warp rows (64 m each)
    const int wn   = wid >> 1;        // 4 warp cols (64 n each)
    const int mBase = blockIdx.y * TILE_M;
    const int nBase = blockIdx.x * TILE_N;

    float acc[4][8][4];               // 128 fp32 accumulators
#pragma unroll
    for (int f = 0; f < 4; ++f)
#pragma unroll
        for (int g = 0; g < 8; ++g)
#pragma unroll
            for (int r = 0; r < 4; ++r) acc[f][g][r] = 0.0f;

    // ---- async copy one chunk: A fp32 (XOR-swizzled 16B slots) + B fp16 ----
    auto issue_stage = [&](int chunk) {
        const int kB = chunk * TILE_K;
        const uint32_t a32 = sbase + A32_OFF + (uint32_t)(chunk & 1) * A32_STAGE;
        const uint32_t bst = sbase + B_OFF + (uint32_t)(chunk % 3) * B_STAGE;
        // A32: 128 rows x 16 slots of 16B (2048 ops / 256 thr = 8 iters)
#pragma unroll
        for (int j = 0; j < 8; ++j) {
            int i = tid + j * THREADS;
            int row = i >> 4, sl = i & 15;
            uint32_t d = a32 + (uint32_t)(row * 256) + (uint32_t)(((sl ^ (row & 15)) << 4));
            cp16(d, Afp + (size_t)(mBase + row) * IN_F + kB + sl * 4);
        }
        // B: 256 rows x 8 slots of 16B
#pragma unroll
        for (int j = 0; j < 8; ++j) {
            int i = tid + j * THREADS;
            int row = i >> 3, kc = i & 7;
            uint32_t d = bst + (uint32_t)(row * 128) + (uint32_t)((kc ^ (row & 7)) << 4);
            cp16(d, g_Wh + (size_t)(nBase + row) * IN_F + kB + kc * 8);
        }
        asm volatile("cp.async.commit_group;" ::: "memory");
    };

    // ---- in-smem A conversion: fp32 stage -> fp16 buffer (ldmatrix layout) ----
    const int cvRow = tid & 31;       // + 32j
    const int cvSl  = tid >> 5;       // fp16 16B-slot 0..7 (= 8 k values)
    auto convertA = [&](int a, int p) {
        const uint32_t a32 = sbase + A32_OFF + (uint32_t)a * A32_STAGE;
        const uint32_t a16 = sbase + A16_OFF + (uint32_t)p * A16_BUF;
#pragma unroll
        for (int j = 0; j < 4; ++j) {
            int row = cvRow + 32 * j;
            uint32_t s0 = a32 + (uint32_t)(row * 256) + (uint32_t)((((2 * cvSl)     ^ (row & 15)) << 4));
            uint32_t s1 = a32 + (uint32_t)(row * 256) + (uint32_t)((((2 * cvSl + 1) ^ (row & 15)) << 4));
            float v0, v1, v2, v3, v4, v5, v6, v7;
            asm volatile("ld.shared.v4.f32 {%0,%1,%2,%3}, [%4];"
                         : "=f"(v0), "=f"(v1), "=f"(v2), "=f"(v3) : "r"(s0));
            asm volatile("ld.shared.v4.f32 {%0,%1,%2,%3}, [%4];"
                         : "=f"(v4), "=f"(v5), "=f"(v6), "=f"(v7) : "r"(s1));
            __half2 h0 = __floats2half2_rn(v0, v1);
            __half2 h1 = __floats2half2_rn(v2, v3);
            __half2 h2 = __floats2half2_rn(v4, v5);
            __half2 h3 = __floats2half2_rn(v6, v7);
            uint32_t d = a16 + (uint32_t)(row * 128) + (uint32_t)((cvSl ^ (row & 7)) << 4);
            asm volatile("st.shared.v4.b32 [%0], {%1,%2,%3,%4};"
                         :: "r"(d),
                            "r"(*reinterpret_cast<uint32_t*>(&h0)),
                            "r"(*reinterpret_cast<uint32_t*>(&h1)),
                            "r"(*reinterpret_cast<uint32_t*>(&h2)),
                            "r"(*reinterpret_cast<uint32_t*>(&h3))
                         : "memory");
        }
    };

    const int rA  = wm * 64 + (lane & 15);
    const int rB  = wn * 64 + (lane & 15);
    const int hi  = lane >> 4;
    const int r7A = rA & 7;
    const int r7B = rB & 7;

    auto compute = [&](int s, int p) {
        const uint32_t sA = sbase + A16_OFF + (uint32_t)p * A16_BUF + (uint32_t)(rA * 128);
        const uint32_t sB = sbase + B_OFF + (uint32_t)s * B_STAGE + (uint32_t)(rB * 128);
        uint32_t a[2][4];
#pragma unroll
        for (int ks = 0; ks < TILE_K / 16; ++ks) {
            const uint32_t cA = (uint32_t)(((2 * ks + hi) ^ r7A) << 4);
            const uint32_t cB = (uint32_t)(((2 * ks + hi) ^ r7B) << 4);
            uint32_t Bf[16];
            ldsm4(a[0], sA + cA);
#pragma unroll
            for (int j = 0; j < 4; ++j) ldsm4(&Bf[4 * j], sB + (uint32_t)(j * 16 * 128) + cB);
#pragma unroll
            for (int f = 0; f < 4; ++f) {
                if (f < 3) ldsm4(a[(f + 1) & 1], sA + (uint32_t)((f + 1) * 16 * 128) + cA);
#pragma unroll
                for (int j = 0; j < 4; ++j) {
                    mma_f16(acc[f][2 * j],     a[f & 1], Bf[4 * j],     Bf[4 * j + 2]);
                    mma_f16(acc[f][2 * j + 1], a[f & 1], Bf[4 * j + 1], Bf[4 * j + 3]);
                }
            }
        }
    };

    // ---- prologue: load chunks 0,1; convert chunk 0 ----
    issue_stage(0);
    issue_stage(1);
    asm volatile("cp.async.wait_group 0;" ::: "memory");
    __syncthreads();
    convertA(0, 0);

    // ---- mainloop: ONE barrier per chunk ----
#pragma unroll 1
    for (int c = 0; c < NC; ++c) {
        if (c > 0 && c + 1 < NC) {
            asm volatile("cp.async.wait_group 0;" ::: "memory");  // chunk c+1 arrived
        }
        __syncthreads();   // orders: prev compute's B/A16 reads, convert writes, cp.async data
        if (c + 2 < NC) issue_stage(c + 2);
        if (c + 1 < NC) convertA((c + 1) & 1, (c + 1) & 1);
        compute(c % 3, c & 1);
    }

    // ---- epilogue: bias + store (64x64 per warp) ----
    const int row0 = mBase + wm * 64 + (lane >> 2);
    const int col0 = nBase + wn * 64 + (lane & 3) * 2;
#pragma unroll
    for (int g = 0; g < 8; ++g) {
        const float b0 = __ldg(bias + col0 + g * 8);
        const float b1 = __ldg(bias + col0 + g * 8 + 1);
#pragma unroll
        for (int f = 0; f < 4; ++f) {
            const int r = row0 + f * 16;
            float2 v0, v1;
            v0.x = acc[f][g][0] + b0; v0.y = acc[f][g][1] + b1;
            v1.x = acc[f][g][2] + b0; v1.y = acc[f][g][3] + b1;
            *reinterpret_cast<float2*>(out + (size_t)r * OUT_F + col0 + g * 8) = v0;
            *reinterpret_cast<float2*>(out + (size_t)(r + 8) * OUT_F + col0 + g * 8) = v1;
        }
    }
}

// ---------------- launch: [prep(W), scatter, gemm] ----------------
extern "C" void kernel_launch(void* const* d_in, const int* in_sizes, int n_in,
                              void* d_out, int out_size) {
    const float* input    = (const float*)d_in[0];   // [8,2048,4096]
    const float* dense_w  = (const float*)d_in[1];   // [4096,4096]
    const float* dense_b  = (const float*)d_in[2];   // [4096]
    const float* sparse_w = (const float*)d_in[3];   // [NNZ]
    const int*   nz_idx   = (const int*)d_in[4];     // [NNZ] sorted
    float* out = (float*)d_out;                      // [8,2048,4096] fp32
    const int nnz = in_sizes[3];

    prep_convert<<<2048, 256>>>(dense_w);
    scatter_fix<<<(nnz + 255) / 256, 256>>>(sparse_w, nz_idx, dense_w, nnz);

    cudaFuncSetAttribute(gemm_kernel, cudaFuncAttributeMaxDynamicSharedMemorySize, SMEM_TOTAL);
    dim3 grid(OUT_F / TILE_N, M_TOTAL / TILE_M);     // 16 x 128 = 2048 CTAs
    gemm_kernel<<<grid, THREADS, SMEM_TOTAL>>>(input, dense_b, out);
}

// round 14
// speedup vs baseline: 1.1406x; 1.1406x over previous
#include <cuda_runtime.h>
#include <cuda_fp16.h>
#include <cstdint>

#define IN_F 4096
#define OUT_F 4096
#define M_TOTAL 16384

#define TILE_M 128
#define TILE_N 256
#define TILE_K 64                       // fp16 elems per chunk = 128B smem rows
#define NC (IN_F / TILE_K)              // 64
#define THREADS 256
#define STAGES 4

// stage layout (bytes): A (128 rows x 128B) | B (256 rows x 128B)
#define A_OFF 0
#define B_OFF (TILE_M * 128)                      // 16384
#define STAGE_BYTES ((TILE_M + TILE_N) * 128)     // 49152
#define SMEM_TOTAL (STAGES * STAGE_BYTES)         // 196608

// ---------------- device scratch ----------------
__device__ __half g_Wh[(size_t)OUT_F * IN_F];
__device__ __half g_Ah[(size_t)M_TOTAL * IN_F];

// ---------------- helpers ----------------
static __device__ __forceinline__ uint32_t smem_u32_of(const void* p) {
    uint32_t r;
    asm("{ .reg .u64 t; cvta.to.shared.u64 t, %1; cvt.u32.u64 %0, t; }" : "=r"(r) : "l"(p));
    return r;
}
static __device__ __forceinline__ void cp16(uint32_t dst, const void* src) {
    asm volatile("cp.async.cg.shared.global [%0], [%1], 16;" :: "r"(dst), "l"(src));
}
static __device__ __forceinline__ void ldsm4(uint32_t* r, uint32_t a) {
    asm volatile("ldmatrix.sync.aligned.m8n8.x4.shared.b16 {%0,%1,%2,%3}, [%4];"
                 : "=r"(r[0]), "=r"(r[1]), "=r"(r[2]), "=r"(r[3]) : "r"(a));
}
static __device__ __forceinline__ void mma_f16(float* d, const uint32_t* a,
                                               uint32_t b0, uint32_t b1) {
    asm volatile(
        "mma.sync.aligned.m16n8k16.row.col.f32.f16.f16.f32 "
        "{%0,%1,%2,%3}, {%4,%5,%6,%7}, {%8,%9}, {%0,%1,%2,%3};"
        : "+f"(d[0]), "+f"(d[1]), "+f"(d[2]), "+f"(d[3])
        : "r"(a[0]), "r"(a[1]), "r"(a[2]), "r"(a[3]), "r"(b0), "r"(b1));
}
static __device__ __forceinline__ uint2 cvt4(float4 v) {
    __half2 p0 = __floats2half2_rn(v.x, v.y);
    __half2 p1 = __floats2half2_rn(v.z, v.w);
    return make_uint2(*reinterpret_cast<uint32_t*>(&p0), *reinterpret_cast<uint32_t*>(&p1));
}

// ---------------- prep kernel 1: fp32 -> fp16 convert (W then A), 2x ILP ----------
__global__ void prep_convert(const float* __restrict__ W, const float* __restrict__ A) {
    const size_t NW4 = (size_t)OUT_F * IN_F / 4;
    const size_t NA4 = (size_t)M_TOTAL * IN_F / 4;
    const size_t NT4 = NW4 + NA4;
    const size_t stride = (size_t)gridDim.x * blockDim.x;
    size_t j0 = (size_t)blockIdx.x * blockDim.x + threadIdx.x;
    for (size_t j = j0; j < NT4; j += 2 * stride) {
        const size_t k = j + stride;
        // element j
        {
            float4 v = (j < NW4) ? reinterpret_cast<const float4*>(W)[j]
                                 : reinterpret_cast<const float4*>(A)[j - NW4];
            uint2 p = cvt4(v);
            if (j < NW4) reinterpret_cast<uint2*>(g_Wh)[j] = p;
            else         reinterpret_cast<uint2*>(g_Ah)[j - NW4] = p;
        }
        // element j + stride (independent load, doubles MLP)
        if (k < NT4) {
            float4 v = (k < NW4) ? reinterpret_cast<const float4*>(W)[k]
                                 : reinterpret_cast<const float4*>(A)[k - NW4];
            uint2 p = cvt4(v);
            if (k < NW4) reinterpret_cast<uint2*>(g_Wh)[k] = p;
            else         reinterpret_cast<uint2*>(g_Ah)[k - NW4] = p;
        }
    }
}

// ---------------- prep kernel 2: sorted scatter, unique-leader rewrite ----------------
__global__ void scatter_fix(const float* __restrict__ sw, const int* __restrict__ idx,
                            const float* __restrict__ W, int nnz) {
    int i = blockIdx.x * blockDim.x + threadIdx.x;
    if (i >= nnz) return;
    int v = idx[i];
    if (i > 0 && idx[i - 1] == v) return;  // not segment leader
    float s = sw[i];
    for (int j = i + 1; j < nnz && idx[j] == v; ++j) s += sw[j];
    g_Wh[v] = __float2half_rn(W[v] + s);
}

// ---------------- GEMM: out[m,n] = sum_k A[m,k]*W[n,k] + bias[n] ----------------
// 128x256 CTA tile, 8 warps (2x4) of 64x64 warp tiles, 4-stage cp.async,
// A-fragment/MMA interleaving inside each k-step. (R10 champion core, unchanged.)
__global__ void __launch_bounds__(THREADS, 1)
gemm_kernel(const float* __restrict__ bias, float* __restrict__ out) {
    extern __shared__ __align__(128) char smem[];
    const uint32_t sbase = smem_u32_of(smem);

    const int tid  = threadIdx.x;
    const int lane = tid & 31;
    const int wid  = tid >> 5;        // 8 warps
    const int wm   = wid & 1;         // 2 warp rows (64 m each)
    const int wn   = wid >> 1;        // 4 warp cols (64 n each)
    const int mBase = blockIdx.y * TILE_M;
    const int nBase = blockIdx.x * TILE_N;

    float acc[4][8][4];               // 128 fp32 accumulators
#pragma unroll
    for (int f = 0; f < 4; ++f)
#pragma unroll
        for (int g = 0; g < 8; ++g)
#pragma unroll
            for (int r = 0; r < 4; ++r) acc[f][g][r] = 0.0f;

    // ---- async copy of one k-chunk into stage s ----
    auto issue_stage = [&](int s, int chunk) {
        const int kB = chunk * TILE_K;
        const uint32_t st = sbase + (uint32_t)s * STAGE_BYTES;
        // A: 128 rows x 8 x 16B (1024 ops / 256 thr = 4 iters)
#pragma unroll
        for (int j = 0; j < 4; ++j) {
            int i = tid + j * THREADS;
            int row = i >> 3, kc = i & 7;
            uint32_t so = (uint32_t)(row * 128) + (uint32_t)((kc ^ (row & 7)) << 4);
            cp16(st + A_OFF + so, g_Ah + (size_t)(mBase + row) * IN_F + kB + kc * 8);
        }
        // B: 256 rows x 8 x 16B (2048 ops / 256 thr = 8 iters)
#pragma unroll
        for (int j = 0; j < 8; ++j) {
            int i = tid + j * THREADS;
            int row = i >> 3, kc = i & 7;
            uint32_t so = (uint32_t)(row * 128) + (uint32_t)((kc ^ (row & 7)) << 4);
            cp16(st + B_OFF + so, g_Wh + (size_t)(nBase + row) * IN_F + kB + kc * 8);
        }
        asm volatile("cp.async.commit_group;" ::: "memory");
    };

    const int rA  = wm * 64 + (lane & 15);
    const int rB  = wn * 64 + (lane & 15);
    const int hi  = lane >> 4;
    const int r7A = rA & 7;
    const int r7B = rB & 7;

    auto compute = [&](int s) {
        const uint32_t st = sbase + (uint32_t)s * STAGE_BYTES;
        const uint32_t sA = st + A_OFF + (uint32_t)(rA * 128);
        const uint32_t sB = st + B_OFF + (uint32_t)(rB * 128);
        uint32_t a[2][4];
#pragma unroll
        for (int ks = 0; ks < TILE_K / 16; ++ks) {
            const uint32_t cA = (uint32_t)(((2 * ks + hi) ^ r7A) << 4);
            const uint32_t cB = (uint32_t)(((2 * ks + hi) ^ r7B) << 4);
            uint32_t Bf[16];
            ldsm4(a[0], sA + cA);
#pragma unroll
            for (int j = 0; j < 4; ++j) ldsm4(&Bf[4 * j], sB + (uint32_t)(j * 16 * 128) + cB);
#pragma unroll
            for (int f = 0; f < 4; ++f) {
                if (f < 3) ldsm4(a[(f + 1) & 1], sA + (uint32_t)((f + 1) * 16 * 128) + cA);
#pragma unroll
                for (int j = 0; j < 4; ++j) {
                    mma_f16(acc[f][2 * j],     a[f & 1], Bf[4 * j],     Bf[4 * j + 2]);
                    mma_f16(acc[f][2 * j + 1], a[f & 1], Bf[4 * j + 1], Bf[4 * j + 3]);
                }
            }
        }
    };

    // ---- 4-stage pipeline, ONE sync per chunk ----
    issue_stage(0, 0);
    issue_stage(1, 1);
    issue_stage(2, 2);
#pragma unroll 1
    for (int c = 0; c < NC; ++c) {
        if (c + 2 < NC) {
            asm volatile("cp.async.wait_group 2;" ::: "memory");
        } else if (c + 1 < NC) {
            asm volatile("cp.async.wait_group 1;" ::: "memory");
        } else {
            asm volatile("cp.async.wait_group 0;" ::: "memory");
        }
        __syncthreads();                 // all warps done reading stage (c-1)%4
        if (c + 3 < NC) issue_stage((c + 3) % STAGES, c + 3);
        compute(c % STAGES);
    }

    // ---- epilogue: bias + store (64x64 per warp) ----
    const int row0 = mBase + wm * 64 + (lane >> 2);
    const int col0 = nBase + wn * 64 + (lane & 3) * 2;
#pragma unroll
    for (int g = 0; g < 8; ++g) {
        const float b0 = __ldg(bias + col0 + g * 8);
        const float b1 = __ldg(bias + col0 + g * 8 + 1);
#pragma unroll
        for (int f = 0; f < 4; ++f) {
            const int r = row0 + f * 16;
            float2 v0, v1;
            v0.x = acc[f][g][0] + b0; v0.y = acc[f][g][1] + b1;
            v1.x = acc[f][g][2] + b0; v1.y = acc[f][g][3] + b1;
            *reinterpret_cast<float2*>(out + (size_t)r * OUT_F + col0 + g * 8) = v0;
            *reinterpret_cast<float2*>(out + (size_t)(r + 8) * OUT_F + col0 + g * 8) = v1;
        }
    }
}

// ---------------- launch: [prep, scatter, gemm] ----------------
extern "C" void kernel_launch(void* const* d_in, const int* in_sizes, int n_in,
                              void* d_out, int out_size) {
    const float* input    = (const float*)d_in[0];   // [8,2048,4096]
    const float* dense_w  = (const float*)d_in[1];   // [4096,4096]
    const float* dense_b  = (const float*)d_in[2];   // [4096]
    const float* sparse_w = (const float*)d_in[3];   // [NNZ]
    const int*   nz_idx   = (const int*)d_in[4];     // [NNZ] sorted
    float* out = (float*)d_out;                      // [8,2048,4096] fp32
    const int nnz = in_sizes[3];

    prep_convert<<<4096, 256>>>(dense_w, input);
    scatter_fix<<<(nnz + 511) / 512, 512>>>(sparse_w, nz_idx, dense_w, nnz);

    cudaFuncSetAttribute(gemm_kernel, cudaFuncAttributeMaxDynamicSharedMemorySize, SMEM_TOTAL);
    dim3 grid(OUT_F / TILE_N, M_TOTAL / TILE_M);     // 16 x 128 = 2048 CTAs, one launch
    gemm_kernel<<<grid, THREADS, SMEM_TOTAL>>>(dense_b, out);
}

// round 15
// speedup vs baseline: 1.1475x; 1.0061x over previous
#include <cuda_runtime.h>
#include <cuda_fp16.h>
#include <cstdint>

#define IN_F 4096
#define OUT_F 4096
#define M_TOTAL 16384

#define TILE_M 128
#define TILE_N 256
#define TILE_K 64                       // fp16 elems per chunk = 128B smem rows
#define NC (IN_F / TILE_K)              // 64
#define THREADS 256
#define STAGES 4

// stage layout (bytes): A (128 rows x 128B) | B (256 rows x 128B)
#define A_OFF 0
#define B_OFF (TILE_M * 128)                      // 16384
#define STAGE_BYTES ((TILE_M + TILE_N) * 128)     // 49152
#define SMEM_TOTAL (STAGES * STAGE_BYTES)         // 196608

// ---------------- device scratch ----------------
__device__ __half g_Wh[(size_t)OUT_F * IN_F];
__device__ __half g_Ah[(size_t)M_TOTAL * IN_F];

// ---------------- helpers ----------------
static __device__ __forceinline__ uint32_t smem_u32_of(const void* p) {
    uint32_t r;
    asm("{ .reg .u64 t; cvta.to.shared.u64 t, %1; cvt.u32.u64 %0, t; }" : "=r"(r) : "l"(p));
    return r;
}
static __device__ __forceinline__ void cp16(uint32_t dst, const void* src) {
    asm volatile("cp.async.cg.shared.global [%0], [%1], 16;" :: "r"(dst), "l"(src));
}
static __device__ __forceinline__ void ldsm4(uint32_t* r, uint32_t a) {
    asm volatile("ldmatrix.sync.aligned.m8n8.x4.shared.b16 {%0,%1,%2,%3}, [%4];"
                 : "=r"(r[0]), "=r"(r[1]), "=r"(r[2]), "=r"(r[3]) : "r"(a));
}
static __device__ __forceinline__ void mma_f16(float* d, const uint32_t* a,
                                               uint32_t b0, uint32_t b1) {
    asm volatile(
        "mma.sync.aligned.m16n8k16.row.col.f32.f16.f16.f32 "
        "{%0,%1,%2,%3}, {%4,%5,%6,%7}, {%8,%9}, {%0,%1,%2,%3};"
        : "+f"(d[0]), "+f"(d[1]), "+f"(d[2]), "+f"(d[3])
        : "r"(a[0]), "r"(a[1]), "r"(a[2]), "r"(a[3]), "r"(b0), "r"(b1));
}

// ---------------- prep kernel 1: fp32 -> fp16 convert (W then A) ----------------
// Simple grid-stride, one float4 per iteration (measured 70us @ 83% HBM — best form).
__global__ void prep_convert(const float* __restrict__ W, const float* __restrict__ A) {
    const size_t NW4 = (size_t)OUT_F * IN_F / 4;
    const size_t NA4 = (size_t)M_TOTAL * IN_F / 4;
    for (size_t j = (size_t)blockIdx.x * blockDim.x + threadIdx.x; j < NW4 + NA4;
         j += (size_t)gridDim.x * blockDim.x) {
        if (j < NW4) {
            float4 v = reinterpret_cast<const float4*>(W)[j];
            __half2 p0 = __floats2half2_rn(v.x, v.y);
            __half2 p1 = __floats2half2_rn(v.z, v.w);
            reinterpret_cast<uint2*>(g_Wh)[j] =
                make_uint2(*reinterpret_cast<uint32_t*>(&p0), *reinterpret_cast<uint32_t*>(&p1));
        } else {
            size_t i = j - NW4;
            float4 v = reinterpret_cast<const float4*>(A)[i];
            __half2 p0 = __floats2half2_rn(v.x, v.y);
            __half2 p1 = __floats2half2_rn(v.z, v.w);
            reinterpret_cast<uint2*>(g_Ah)[i] =
                make_uint2(*reinterpret_cast<uint32_t*>(&p0), *reinterpret_cast<uint32_t*>(&p1));
        }
    }
}

// ---------------- prep kernel 2: sorted scatter, unique-leader rewrite ----------------
__global__ void scatter_fix(const float* __restrict__ sw, const int* __restrict__ idx,
                            const float* __restrict__ W, int nnz) {
    int i = blockIdx.x * blockDim.x + threadIdx.x;
    if (i >= nnz) return;
    int v = idx[i];
    if (i > 0 && idx[i - 1] == v) return;  // not segment leader
    float s = sw[i];
    for (int j = i + 1; j < nnz && idx[j] == v; ++j) s += sw[j];
    g_Wh[v] = __float2half_rn(W[v] + s);
}

// ---------------- GEMM: out[m,n] = sum_k A[m,k]*W[n,k] + bias[n] ----------------
// 128x256 CTA tile, 8 warps (2x4) of 64x64 warp tiles, 4-stage cp.async,
// A-fragment/MMA interleaving inside each k-step. (R10 champion core, unchanged.)
__global__ void __launch_bounds__(THREADS, 1)
gemm_kernel(const float* __restrict__ bias, float* __restrict__ out) {
    extern __shared__ __align__(128) char smem[];
    const uint32_t sbase = smem_u32_of(smem);

    const int tid  = threadIdx.x;
    const int lane = tid & 31;
    const int wid  = tid >> 5;        // 8 warps
    const int wm   = wid & 1;         // 2 warp rows (64 m each)
    const int wn   = wid >> 1;        // 4 warp cols (64 n each)
    const int mBase = blockIdx.y * TILE_M;
    const int nBase = blockIdx.x * TILE_N;

    float acc[4][8][4];               // 128 fp32 accumulators
#pragma unroll
    for (int f = 0; f < 4; ++f)
#pragma unroll
        for (int g = 0; g < 8; ++g)
#pragma unroll
            for (int r = 0; r < 4; ++r) acc[f][g][r] = 0.0f;

    // ---- async copy of one k-chunk into stage s ----
    auto issue_stage = [&](int s, int chunk) {
        const int kB = chunk * TILE_K;
        const uint32_t st = sbase + (uint32_t)s * STAGE_BYTES;
        // A: 128 rows x 8 x 16B (1024 ops / 256 thr = 4 iters)
#pragma unroll
        for (int j = 0; j < 4; ++j) {
            int i = tid + j * THREADS;
            int row = i >> 3, kc = i & 7;
            uint32_t so = (uint32_t)(row * 128) + (uint32_t)((kc ^ (row & 7)) << 4);
            cp16(st + A_OFF + so, g_Ah + (size_t)(mBase + row) * IN_F + kB + kc * 8);
        }
        // B: 256 rows x 8 x 16B (2048 ops / 256 thr = 8 iters)
#pragma unroll
        for (int j = 0; j < 8; ++j) {
            int i = tid + j * THREADS;
            int row = i >> 3, kc = i & 7;
            uint32_t so = (uint32_t)(row * 128) + (uint32_t)((kc ^ (row & 7)) << 4);
            cp16(st + B_OFF + so, g_Wh + (size_t)(nBase + row) * IN_F + kB + kc * 8);
        }
        asm volatile("cp.async.commit_group;" ::: "memory");
    };

    const int rA  = wm * 64 + (lane & 15);
    const int rB  = wn * 64 + (lane & 15);
    const int hi  = lane >> 4;
    const int r7A = rA & 7;
    const int r7B = rB & 7;

    auto compute = [&](int s) {
        const uint32_t st = sbase + (uint32_t)s * STAGE_BYTES;
        const uint32_t sA = st + A_OFF + (uint32_t)(rA * 128);
        const uint32_t sB = st + B_OFF + (uint32_t)(rB * 128);
        uint32_t a[2][4];
#pragma unroll
        for (int ks = 0; ks < TILE_K / 16; ++ks) {
            const uint32_t cA = (uint32_t)(((2 * ks + hi) ^ r7A) << 4);
            const uint32_t cB = (uint32_t)(((2 * ks + hi) ^ r7B) << 4);
            uint32_t Bf[16];
            ldsm4(a[0], sA + cA);
#pragma unroll
            for (int j = 0; j < 4; ++j) ldsm4(&Bf[4 * j], sB + (uint32_t)(j * 16 * 128) + cB);
#pragma unroll
            for (int f = 0; f < 4; ++f) {
                if (f < 3) ldsm4(a[(f + 1) & 1], sA + (uint32_t)((f + 1) * 16 * 128) + cA);
#pragma unroll
                for (int j = 0; j < 4; ++j) {
                    mma_f16(acc[f][2 * j],     a[f & 1], Bf[4 * j],     Bf[4 * j + 2]);
                    mma_f16(acc[f][2 * j + 1], a[f & 1], Bf[4 * j + 1], Bf[4 * j + 3]);
                }
            }
        }
    };

    // ---- 4-stage pipeline, ONE sync per chunk ----
    issue_stage(0, 0);
    issue_stage(1, 1);
    issue_stage(2, 2);
#pragma unroll 1
    for (int c = 0; c < NC; ++c) {
        if (c + 2 < NC) {
            asm volatile("cp.async.wait_group 2;" ::: "memory");
        } else if (c + 1 < NC) {
            asm volatile("cp.async.wait_group 1;" ::: "memory");
        } else {
            asm volatile("cp.async.wait_group 0;" ::: "memory");
        }
        __syncthreads();                 // all warps done reading stage (c-1)%4
        if (c + 3 < NC) issue_stage((c + 3) % STAGES, c + 3);
        compute(c % STAGES);
    }

    // ---- epilogue: bias + store (64x64 per warp) ----
    const int row0 = mBase + wm * 64 + (lane >> 2);
    const int col0 = nBase + wn * 64 + (lane & 3) * 2;
#pragma unroll
    for (int g = 0; g < 8; ++g) {
        const float b0 = __ldg(bias + col0 + g * 8);
        const float b1 = __ldg(bias + col0 + g * 8 + 1);
#pragma unroll
        for (int f = 0; f < 4; ++f) {
            const int r = row0 + f * 16;
            float2 v0, v1;
            v0.x = acc[f][g][0] + b0; v0.y = acc[f][g][1] + b1;
            v1.x = acc[f][g][2] + b0; v1.y = acc[f][g][3] + b1;
            *reinterpret_cast<float2*>(out + (size_t)r * OUT_F + col0 + g * 8) = v0;
            *reinterpret_cast<float2*>(out + (size_t)(r + 8) * OUT_F + col0 + g * 8) = v1;
        }
    }
}

// ---------------- launch: [prep, scatter, gemm] ----------------
extern "C" void kernel_launch(void* const* d_in, const int* in_sizes, int n_in,
                              void* d_out, int out_size) {
    const float* input    = (const float*)d_in[0];   // [8,2048,4096]
    const float* dense_w  = (const float*)d_in[1];   // [4096,4096]
    const float* dense_b  = (const float*)d_in[2];   // [4096]
    const float* sparse_w = (const float*)d_in[3];   // [NNZ]
    const int*   nz_idx   = (const int*)d_in[4];     // [NNZ] sorted
    float* out = (float*)d_out;                      // [8,2048,4096] fp32
    const int nnz = in_sizes[3];

    prep_convert<<<8192, 256>>>(dense_w, input);
    scatter_fix<<<(nnz + 511) / 512, 512>>>(sparse_w, nz_idx, dense_w, nnz);

    cudaFuncSetAttribute(gemm_kernel, cudaFuncAttributeMaxDynamicSharedMemorySize, SMEM_TOTAL);
    dim3 grid(OUT_F / TILE_N, M_TOTAL / TILE_M);     // 16 x 128 = 2048 CTAs, one launch
    gemm_kernel<<<grid, THREADS, SMEM_TOTAL>>>(dense_b, out);
}